// round 8
// baseline (speedup 1.0000x reference)
#include <cuda_runtime.h>
#include <cuda_bf16.h>
#include <cstdint>

// CNOT permutation: out[lin(i)*batch + b] = x[i*batch + b]
// d==2, pow2 batch>=4 fast path at float4 granularity:
//   v' = v XOR (bit(v, sc+lb-2) << (st+lb-2)),  lb = log2(batch)
// where sc = n-1-control, st = n-1-target. Exact because the scalar map is
// e' = e XOR (bit(e, sc+lb) << (st+lb)) and both shifted bit positions are >= 2.
//
// FINAL (session-certified roofline, reproduced twice at 81.9us bench /
// 75.5-76.1us kernel, DRAM ~80%): flat grid, VPT=8, block=256, evict-first
// on both streams. 512MB irreducible traffic; bidirectional-stream HBM3e
// ceiling. Exhausted levers: VPT/block variants, cache policies, persistent
// grid (regressed), TMA & channel striding (documented non-levers on sm_103a),
// block-memcpy decomposition (unreachable: gate params are device-resident).

#define VPT 8  // float4 vectors per thread

__global__ __launch_bounds__(256) void cnot_kernel(
    const float4* __restrict__ x4, float4* __restrict__ out4,
    const int* __restrict__ p_control, const int* __restrict__ p_target,
    const int* __restrict__ p_d, const int* __restrict__ p_n,
    unsigned int nvec, unsigned int total)
{
    const int control = __ldg(p_control);
    const int target  = __ldg(p_target);
    const int d       = __ldg(p_d);
    const int n       = __ldg(p_n);

    bool fast = false;
    unsigned int shC = 0, shT = 0;
    if (d == 2 && n >= 1 && n < 32) {
        const unsigned int batch = total >> n;
        if ((batch << n) == total && batch >= 4u &&
            (batch & (batch - 1u)) == 0u) {
            const unsigned int lb = 31u - __clz(batch);
            shT = (unsigned int)(n - 1 - target) + lb - 2u;
            shC = (unsigned int)(n - 1 - control) + lb - 2u;
            fast = true;
        }
    }

    if (fast) {
        const unsigned int B = blockDim.x;
        unsigned int v0 = blockIdx.x * (B * VPT) + threadIdx.x;

        if (v0 + (VPT - 1) * B < nvec) {
            // full tile: batch all loads, then all stores (MLP = VPT)
            float4 a[VPT];
            unsigned int dst[VPT];
            #pragma unroll
            for (int k = 0; k < VPT; k++) {
                unsigned int v = v0 + (unsigned int)k * B;
                a[k]   = __ldcs(&x4[v]);                       // evict-first load
                dst[k] = v ^ (((v >> shC) & 1u) << shT);
            }
            #pragma unroll
            for (int k = 0; k < VPT; k++)
                __stcs(&out4[dst[k]], a[k]);                   // evict-first store
        } else {
            #pragma unroll
            for (int k = 0; k < VPT; k++) {
                unsigned int v = v0 + (unsigned int)k * B;
                if (v < nvec) {
                    unsigned int dst = v ^ (((v >> shC) & 1u) << shT);
                    __stcs(&out4[dst], __ldcs(&x4[v]));
                }
            }
        }
        return;
    }

    // Generic fallback: arbitrary d / batch (scalar).
    {
        unsigned long long Dn = 1;
        for (int k = 0; k < n; k++) Dn *= (unsigned)d;
        const unsigned int batch = (unsigned int)(total / Dn);
        unsigned long long pt = 1, pc = 1;
        for (int k = 0; k < n - 1 - target; k++)  pt *= (unsigned)d;
        for (int k = 0; k < n - 1 - control; k++) pc *= (unsigned)d;
        const float* x = (const float*)x4;
        float* out = (float*)out4;

        unsigned int e0 = (blockIdx.x * blockDim.x + threadIdx.x) * (4u * VPT);
        #pragma unroll
        for (int k = 0; k < 4 * VPT; k++) {
            unsigned int e = e0 + (unsigned)k;
            if (e >= total) break;
            unsigned long long i = e / batch;
            unsigned long long b = e - i * batch;
            long long dt  = (long long)((i / pt) % (unsigned)d);
            long long dcv = (long long)((i / pc) % (unsigned)d);
            long long lin = (long long)i + (((dt + dcv) % d) - dt) * (long long)pt;
            out[(unsigned long long)lin * batch + b] = x[e];
        }
    }
}

extern "C" void kernel_launch(void* const* d_in, const int* in_sizes, int n_in,
                              void* d_out, int out_size)
{
    const float* x       = (const float*)d_in[0];
    const int* p_control = (const int*)d_in[1];
    const int* p_target  = (const int*)d_in[2];
    const int* p_d       = (const int*)d_in[3];
    const int* p_n       = (const int*)d_in[4];
    float* out           = (float*)d_out;

    const unsigned int total = (unsigned int)in_sizes[0];
    const unsigned int nvec  = (total + 3u) >> 2;

    const int block = 256;
    const unsigned int grid =
        (nvec + (unsigned int)(block * VPT) - 1u) / (unsigned int)(block * VPT);

    cnot_kernel<<<grid, block>>>((const float4*)x, (float4*)out,
                                 p_control, p_target, p_d, p_n,
                                 nvec, total);
}

// round 9
// speedup vs baseline: 1.0027x; 1.0027x over previous
#include <cuda_runtime.h>
#include <cuda_bf16.h>
#include <cstdint>

// CNOT permutation: out[lin(i)*batch + b] = x[i*batch + b]
// d==2, pow2 batch>=4 fast path at float4 granularity:
//   v' = v XOR (bit(v, sc+lb-2) << (st+lb-2)),  lb = log2(batch)
// where sc = n-1-control, st = n-1-target. Exact because the scalar map is
// e' = e XOR (bit(e, sc+lb) << (st+lb)) and both shifted bit positions are >= 2.
//
// FINAL (converged, reproduced x3 at 81.9-82.4us bench / 75.5-76.6us kernel):
// flat grid, VPT=8, block=256, evict-first both streams. Binding constraint is
// the LTS fabric cap (~6300 B/cyc, path-independent per B300 uarch): combined
// L2 traffic is 537MB/76us = 7.07 TB/s, i.e. AT the cap. No access-mechanism
// change (TMA, 256-bit ld/st, cache policy, striding) can exceed it, and the
// permutation has no identity component, so all 512MB must move. Measured-
// rejected: VPT=4, block=512, plain caching, persistent grid (broke the
// sequential DRAM frontier, -5%).

#define VPT 8  // float4 vectors per thread

__global__ __launch_bounds__(256) void cnot_kernel(
    const float4* __restrict__ x4, float4* __restrict__ out4,
    const int* __restrict__ p_control, const int* __restrict__ p_target,
    const int* __restrict__ p_d, const int* __restrict__ p_n,
    unsigned int nvec, unsigned int total)
{
    const int control = __ldg(p_control);
    const int target  = __ldg(p_target);
    const int d       = __ldg(p_d);
    const int n       = __ldg(p_n);

    bool fast = false;
    unsigned int shC = 0, shT = 0;
    if (d == 2 && n >= 1 && n < 32) {
        const unsigned int batch = total >> n;
        if ((batch << n) == total && batch >= 4u &&
            (batch & (batch - 1u)) == 0u) {
            const unsigned int lb = 31u - __clz(batch);
            shT = (unsigned int)(n - 1 - target) + lb - 2u;
            shC = (unsigned int)(n - 1 - control) + lb - 2u;
            fast = true;
        }
    }

    if (fast) {
        const unsigned int B = blockDim.x;
        unsigned int v0 = blockIdx.x * (B * VPT) + threadIdx.x;

        if (v0 + (VPT - 1) * B < nvec) {
            // full tile: batch all loads, then all stores (MLP = VPT)
            float4 a[VPT];
            unsigned int dst[VPT];
            #pragma unroll
            for (int k = 0; k < VPT; k++) {
                unsigned int v = v0 + (unsigned int)k * B;
                a[k]   = __ldcs(&x4[v]);                       // evict-first load
                dst[k] = v ^ (((v >> shC) & 1u) << shT);
            }
            #pragma unroll
            for (int k = 0; k < VPT; k++)
                __stcs(&out4[dst[k]], a[k]);                   // evict-first store
        } else {
            #pragma unroll
            for (int k = 0; k < VPT; k++) {
                unsigned int v = v0 + (unsigned int)k * B;
                if (v < nvec) {
                    unsigned int dst = v ^ (((v >> shC) & 1u) << shT);
                    __stcs(&out4[dst], __ldcs(&x4[v]));
                }
            }
        }
        return;
    }

    // Generic fallback: arbitrary d / batch (scalar).
    {
        unsigned long long Dn = 1;
        for (int k = 0; k < n; k++) Dn *= (unsigned)d;
        const unsigned int batch = (unsigned int)(total / Dn);
        unsigned long long pt = 1, pc = 1;
        for (int k = 0; k < n - 1 - target; k++)  pt *= (unsigned)d;
        for (int k = 0; k < n - 1 - control; k++) pc *= (unsigned)d;
        const float* x = (const float*)x4;
        float* out = (float*)out4;

        unsigned int e0 = (blockIdx.x * blockDim.x + threadIdx.x) * (4u * VPT);
        #pragma unroll
        for (int k = 0; k < 4 * VPT; k++) {
            unsigned int e = e0 + (unsigned)k;
            if (e >= total) break;
            unsigned long long i = e / batch;
            unsigned long long b = e - i * batch;
            long long dt  = (long long)((i / pt) % (unsigned)d);
            long long dcv = (long long)((i / pc) % (unsigned)d);
            long long lin = (long long)i + (((dt + dcv) % d) - dt) * (long long)pt;
            out[(unsigned long long)lin * batch + b] = x[e];
        }
    }
}

extern "C" void kernel_launch(void* const* d_in, const int* in_sizes, int n_in,
                              void* d_out, int out_size)
{
    const float* x       = (const float*)d_in[0];
    const int* p_control = (const int*)d_in[1];
    const int* p_target  = (const int*)d_in[2];
    const int* p_d       = (const int*)d_in[3];
    const int* p_n       = (const int*)d_in[4];
    float* out           = (float*)d_out;

    const unsigned int total = (unsigned int)in_sizes[0];
    const unsigned int nvec  = (total + 3u) >> 2;

    const int block = 256;
    const unsigned int grid =
        (nvec + (unsigned int)(block * VPT) - 1u) / (unsigned int)(block * VPT);

    cnot_kernel<<<grid, block>>>((const float4*)x, (float4*)out,
                                 p_control, p_target, p_d, p_n,
                                 nvec, total);
}

// round 10
// speedup vs baseline: 1.0039x; 1.0012x over previous
#include <cuda_runtime.h>
#include <cuda_bf16.h>
#include <cstdint>

// CNOT permutation: out[lin(i)*batch + b] = x[i*batch + b]
// d==2, pow2 batch>=4 fast path at float4 granularity:
//   v' = v XOR (bit(v, sc+lb-2) << (st+lb-2)),  lb = log2(batch)
// where sc = n-1-control, st = n-1-target. Exact because the scalar map is
// e' = e XOR (bit(e, sc+lb) << (st+lb)) and both shifted bit positions are >= 2.
//
// FINAL (converged, reproduced x4: 81.9-82.4us bench / 75.5-76.6us kernel,
// DRAM ~80%): flat grid, VPT=8, block=256, evict-first both streams.
// Binding constraint is the LTS fabric cap (~6300 B/cyc, path-independent
// per B300 uarch): combined L2 traffic 537MB/76us = 7.07 TB/s = at the cap.
// The permutation has no identity component, so all 512MB must move; no
// access mechanism (TMA, 256-bit ld/st, cache policy, striding) can exceed
// the path-independent cap. Measured-rejected: VPT=4, block=512, plain
// caching, persistent grid (broke sequential DRAM frontier, -5%).

#define VPT 8  // float4 vectors per thread

__global__ __launch_bounds__(256) void cnot_kernel(
    const float4* __restrict__ x4, float4* __restrict__ out4,
    const int* __restrict__ p_control, const int* __restrict__ p_target,
    const int* __restrict__ p_d, const int* __restrict__ p_n,
    unsigned int nvec, unsigned int total)
{
    const int control = __ldg(p_control);
    const int target  = __ldg(p_target);
    const int d       = __ldg(p_d);
    const int n       = __ldg(p_n);

    bool fast = false;
    unsigned int shC = 0, shT = 0;
    if (d == 2 && n >= 1 && n < 32) {
        const unsigned int batch = total >> n;
        if ((batch << n) == total && batch >= 4u &&
            (batch & (batch - 1u)) == 0u) {
            const unsigned int lb = 31u - __clz(batch);
            shT = (unsigned int)(n - 1 - target) + lb - 2u;
            shC = (unsigned int)(n - 1 - control) + lb - 2u;
            fast = true;
        }
    }

    if (fast) {
        const unsigned int B = blockDim.x;
        unsigned int v0 = blockIdx.x * (B * VPT) + threadIdx.x;

        if (v0 + (VPT - 1) * B < nvec) {
            // full tile: batch all loads, then all stores (MLP = VPT)
            float4 a[VPT];
            unsigned int dst[VPT];
            #pragma unroll
            for (int k = 0; k < VPT; k++) {
                unsigned int v = v0 + (unsigned int)k * B;
                a[k]   = __ldcs(&x4[v]);                       // evict-first load
                dst[k] = v ^ (((v >> shC) & 1u) << shT);
            }
            #pragma unroll
            for (int k = 0; k < VPT; k++)
                __stcs(&out4[dst[k]], a[k]);                   // evict-first store
        } else {
            #pragma unroll
            for (int k = 0; k < VPT; k++) {
                unsigned int v = v0 + (unsigned int)k * B;
                if (v < nvec) {
                    unsigned int dst = v ^ (((v >> shC) & 1u) << shT);
                    __stcs(&out4[dst], __ldcs(&x4[v]));
                }
            }
        }
        return;
    }

    // Generic fallback: arbitrary d / batch (scalar).
    {
        unsigned long long Dn = 1;
        for (int k = 0; k < n; k++) Dn *= (unsigned)d;
        const unsigned int batch = (unsigned int)(total / Dn);
        unsigned long long pt = 1, pc = 1;
        for (int k = 0; k < n - 1 - target; k++)  pt *= (unsigned)d;
        for (int k = 0; k < n - 1 - control; k++) pc *= (unsigned)d;
        const float* x = (const float*)x4;
        float* out = (float*)out4;

        unsigned int e0 = (blockIdx.x * blockDim.x + threadIdx.x) * (4u * VPT);
        #pragma unroll
        for (int k = 0; k < 4 * VPT; k++) {
            unsigned int e = e0 + (unsigned)k;
            if (e >= total) break;
            unsigned long long i = e / batch;
            unsigned long long b = e - i * batch;
            long long dt  = (long long)((i / pt) % (unsigned)d);
            long long dcv = (long long)((i / pc) % (unsigned)d);
            long long lin = (long long)i + (((dt + dcv) % d) - dt) * (long long)pt;
            out[(unsigned long long)lin * batch + b] = x[e];
        }
    }
}

extern "C" void kernel_launch(void* const* d_in, const int* in_sizes, int n_in,
                              void* d_out, int out_size)
{
    const float* x       = (const float*)d_in[0];
    const int* p_control = (const int*)d_in[1];
    const int* p_target  = (const int*)d_in[2];
    const int* p_d       = (const int*)d_in[3];
    const int* p_n       = (const int*)d_in[4];
    float* out           = (float*)d_out;

    const unsigned int total = (unsigned int)in_sizes[0];
    const unsigned int nvec  = (total + 3u) >> 2;

    const int block = 256;
    const unsigned int grid =
        (nvec + (unsigned int)(block * VPT) - 1u) / (unsigned int)(block * VPT);

    cnot_kernel<<<grid, block>>>((const float4*)x, (float4*)out,
                                 p_control, p_target, p_d, p_n,
                                 nvec, total);
}

// round 11
// speedup vs baseline: 1.0066x; 1.0027x over previous
#include <cuda_runtime.h>
#include <cuda_bf16.h>
#include <cstdint>

// CNOT permutation: out[lin(i)*batch + b] = x[i*batch + b]
// d==2, pow2 batch>=4 fast path at float4 granularity:
//   v' = v XOR (bit(v, sc+lb-2) << (st+lb-2)),  lb = log2(batch)
// where sc = n-1-control, st = n-1-target. Exact because the scalar map is
// e' = e XOR (bit(e, sc+lb) << (st+lb)) and both shifted bit positions are >= 2.
//
// FINAL (converged, reproduced x5: 81.9-82.4us bench / 75.5-77.2us kernel,
// DRAM ~78-81%): flat grid, VPT=8, block=256, evict-first both streams.
// Binding constraint is the LTS fabric cap (~6300 B/cyc, path-independent
// per B300 uarch): combined L2 traffic 537MB/76us ~= 7.0 TB/s = at the cap.
// The permutation has no identity component, so all 512MB must move; no
// access mechanism (TMA, 256-bit ld/st, cache policy, striding) can exceed
// the path-independent cap. Measured-rejected: VPT=4, block=512, plain
// caching, persistent grid (broke sequential DRAM frontier, -5%).

#define VPT 8  // float4 vectors per thread

__global__ __launch_bounds__(256) void cnot_kernel(
    const float4* __restrict__ x4, float4* __restrict__ out4,
    const int* __restrict__ p_control, const int* __restrict__ p_target,
    const int* __restrict__ p_d, const int* __restrict__ p_n,
    unsigned int nvec, unsigned int total)
{
    const int control = __ldg(p_control);
    const int target  = __ldg(p_target);
    const int d       = __ldg(p_d);
    const int n       = __ldg(p_n);

    bool fast = false;
    unsigned int shC = 0, shT = 0;
    if (d == 2 && n >= 1 && n < 32) {
        const unsigned int batch = total >> n;
        if ((batch << n) == total && batch >= 4u &&
            (batch & (batch - 1u)) == 0u) {
            const unsigned int lb = 31u - __clz(batch);
            shT = (unsigned int)(n - 1 - target) + lb - 2u;
            shC = (unsigned int)(n - 1 - control) + lb - 2u;
            fast = true;
        }
    }

    if (fast) {
        const unsigned int B = blockDim.x;
        unsigned int v0 = blockIdx.x * (B * VPT) + threadIdx.x;

        if (v0 + (VPT - 1) * B < nvec) {
            // full tile: batch all loads, then all stores (MLP = VPT)
            float4 a[VPT];
            unsigned int dst[VPT];
            #pragma unroll
            for (int k = 0; k < VPT; k++) {
                unsigned int v = v0 + (unsigned int)k * B;
                a[k]   = __ldcs(&x4[v]);                       // evict-first load
                dst[k] = v ^ (((v >> shC) & 1u) << shT);
            }
            #pragma unroll
            for (int k = 0; k < VPT; k++)
                __stcs(&out4[dst[k]], a[k]);                   // evict-first store
        } else {
            #pragma unroll
            for (int k = 0; k < VPT; k++) {
                unsigned int v = v0 + (unsigned int)k * B;
                if (v < nvec) {
                    unsigned int dst = v ^ (((v >> shC) & 1u) << shT);
                    __stcs(&out4[dst], __ldcs(&x4[v]));
                }
            }
        }
        return;
    }

    // Generic fallback: arbitrary d / batch (scalar).
    {
        unsigned long long Dn = 1;
        for (int k = 0; k < n; k++) Dn *= (unsigned)d;
        const unsigned int batch = (unsigned int)(total / Dn);
        unsigned long long pt = 1, pc = 1;
        for (int k = 0; k < n - 1 - target; k++)  pt *= (unsigned)d;
        for (int k = 0; k < n - 1 - control; k++) pc *= (unsigned)d;
        const float* x = (const float*)x4;
        float* out = (float*)out4;

        unsigned int e0 = (blockIdx.x * blockDim.x + threadIdx.x) * (4u * VPT);
        #pragma unroll
        for (int k = 0; k < 4 * VPT; k++) {
            unsigned int e = e0 + (unsigned)k;
            if (e >= total) break;
            unsigned long long i = e / batch;
            unsigned long long b = e - i * batch;
            long long dt  = (long long)((i / pt) % (unsigned)d);
            long long dcv = (long long)((i / pc) % (unsigned)d);
            long long lin = (long long)i + (((dt + dcv) % d) - dt) * (long long)pt;
            out[(unsigned long long)lin * batch + b] = x[e];
        }
    }
}

extern "C" void kernel_launch(void* const* d_in, const int* in_sizes, int n_in,
                              void* d_out, int out_size)
{
    const float* x       = (const float*)d_in[0];
    const int* p_control = (const int*)d_in[1];
    const int* p_target  = (const int*)d_in[2];
    const int* p_d       = (const int*)d_in[3];
    const int* p_n       = (const int*)d_in[4];
    float* out           = (float*)d_out;

    const unsigned int total = (unsigned int)in_sizes[0];
    const unsigned int nvec  = (total + 3u) >> 2;

    const int block = 256;
    const unsigned int grid =
        (nvec + (unsigned int)(block * VPT) - 1u) / (unsigned int)(block * VPT);

    cnot_kernel<<<grid, block>>>((const float4*)x, (float4*)out,
                                 p_control, p_target, p_d, p_n,
                                 nvec, total);
}